// round 14
// baseline (speedup 1.0000x reference)
#include <cuda_runtime.h>

// L_spa loss, single fused kernel (v4: zero-halo via inter-block handoff).
// org, enhance: [32, 3, 512, 512] fp32.
// d[b,ph,pw] = (sum over 3ch x 4x4 block of (org-enh)) / 48   [32,128,128]
// loss = mean over pixels of 4 shift-diff squares (zero padding).
//
// Loss algebra: sum = horizontal terms + 2*(d[r]-d[r+1])^2 per interior
// vertical pair (assigned to upper row) + d[0]^2 + d[127]^2 edge terms.
//
// v4 change vs v3 (which measured 35.9us, DRAM 73%): each block pools ONLY
// its 16 own rows (no halo recompute; 214MB -> 201MB DRAM). The boundary
// pair (row s+15 vs s+16) uses the pooled row 0 published by the block
// below through global scratch + flag handshake. Chain band k waits on
// k+1 only (acyclic); all 256 blocks resident in one wave at 2 CTAs/SM,
// so the spin cannot deadlock. Last-finishing block resets flags and
// accumulators so the kernel is graph-replay deterministic.

#define HWROW4   128                 // 512-float raw row = 128 float4
#define CH4      (512 * HWROW4)     // float4 per channel
#define IMG4     (3 * CH4)          // float4 per image
#define PH       128                 // pooled H = W
#define BAND     16                  // pooled rows per block
#define NPIX     (32 * PH * PH)
#define NBANDS   8
#define NBLOCKS  (NBANDS * 32)

__device__ float          g_acc;                     // zero-init
__device__ unsigned       g_count;                   // zero-init
__device__ float          g_edge[32][NBANDS][PH];    // pooled row 0 per band
__device__ volatile int   g_flag[32 * NBANDS];       // zero-init

__global__ void __launch_bounds__(512, 2) spa_fused_kernel(
    const float4* __restrict__ org, const float4* __restrict__ enh,
    float* __restrict__ out) {
    __shared__ float tile[BAND][PH];       // 8192 B
    __shared__ float edge_sm[PH];
    __shared__ float warp_sums[16];

    const int band = blockIdx.x;           // 0..7
    const int b    = blockIdx.y;           // 0..31
    const int tid  = threadIdx.x;
    const int s    = band * BAND;
    const int ibase = b * IMG4;

    // ---- Phase 1: pool own 16 rows. 2048 items / 512 thr = 4 full iters.
#pragma unroll
    for (int k = 0; k < (BAND * PH) / 512; k++) {
        int i   = k * 512 + tid;
        int r   = i >> 7;                  // 0..15
        int pw  = i & 127;
        int base = ibase + ((s + r) * 4) * HWROW4 + pw;
        float sum = 0.0f;
#pragma unroll
        for (int c = 0; c < 3; c++) {
#pragma unroll
            for (int dy = 0; dy < 4; dy++) {
                float4 o = __ldg(&org[base + c * CH4 + dy * HWROW4]);
                float4 e = __ldg(&enh[base + c * CH4 + dy * HWROW4]);
                sum += (o.x - e.x) + (o.y - e.y) + (o.z - e.z) + (o.w - e.w);
            }
        }
        tile[r][pw] = sum * (1.0f / 48.0f);
    }
    __syncthreads();

    // ---- Handoff: publish own pooled row 0; fetch neighbor's row 0.
    if (tid < PH) g_edge[b][band][tid] = tile[0][tid];
    __syncthreads();                       // row-0 writes done block-wide
    if (tid == 0) {
        __threadfence();                   // make g_edge visible device-wide
        g_flag[b * NBANDS + band] = 1;     // release
        if (band < NBANDS - 1) {
            while (g_flag[b * NBANDS + band + 1] == 0) { }   // acquire spin
            __threadfence();
        }
    }
    __syncthreads();
    if (band < NBANDS - 1 && tid < PH)
        edge_sm[tid] = g_edge[b][band + 1][tid];
    __syncthreads();

    // ---- Phase 2: loss over the 16 owned rows (all smem).
    float t = 0.0f;
#pragma unroll
    for (int k = 0; k < (BAND * PH) / 512; k++) {
        int i  = k * 512 + tid;
        int r  = i >> 7;                   // 0..15
        int pw = i & 127;
        int gr = s + r;
        float c  = tile[r][pw];
        float l  = (pw > 0)      ? tile[r][pw - 1] : 0.0f;
        float rr = (pw < PH - 1) ? tile[r][pw + 1] : 0.0f;
        t += (c - l) * (c - l) + (c - rr) * (c - rr);
        if (r < BAND - 1) {                // interior pair, counted x2
            float bl = tile[r + 1][pw];
            t += 2.0f * (c - bl) * (c - bl);
        } else if (band < NBANDS - 1) {    // cross-band pair via handoff
            float bl = edge_sm[pw];
            t += 2.0f * (c - bl) * (c - bl);
        } else {                           // bottom image edge
            t += c * c;
        }
        if (gr == 0) t += c * c;           // top image edge
    }

    // ---- Phase 3: block reduce + last-block finalize & reset.
#pragma unroll
    for (int off = 16; off > 0; off >>= 1)
        t += __shfl_down_sync(0xFFFFFFFFu, t, off);
    int lane = tid & 31, wid = tid >> 5;
    if (lane == 0) warp_sums[wid] = t;
    __syncthreads();
    if (wid == 0) {
        float v = (lane < 16) ? warp_sums[lane] : 0.0f;
#pragma unroll
        for (int off = 8; off > 0; off >>= 1)
            v += __shfl_down_sync(0xFFFFFFFFu, v, off);
        if (lane == 0) {
            atomicAdd(&g_acc, v);
            __threadfence();
            unsigned done = atomicAdd(&g_count, 1u);
            if (done == NBLOCKS - 1) {     // every block has finished
                out[0] = g_acc * (1.0f / (float)NPIX);
                g_acc   = 0.0f;
                g_count = 0u;
                for (int j = 0; j < 32 * NBANDS; j++) g_flag[j] = 0;
            }
        }
    }
}

extern "C" void kernel_launch(void* const* d_in, const int* in_sizes, int n_in,
                              void* d_out, int out_size) {
    const float4* org = (const float4*)d_in[0];
    const float4* enh = (const float4*)d_in[1];
    float* out = (float*)d_out;
    spa_fused_kernel<<<dim3(NBANDS, 32), 512>>>(org, enh, out);
}

// round 16
// speedup vs baseline: 1.0779x; 1.0779x over previous
#include <cuda_runtime.h>

// L_spa loss, fused single kernel (v5 = R2 geometry + one-sided halo).
// org, enhance: [32, 3, 512, 512] fp32.
// d[b,ph,pw] = (sum over 3ch x 4x4 block of (org-enh)) / 48   [32,128,128]
// loss = mean over pixels of 4 shift-diff squares (zero padding).
//
// Loss algebra: horizontal terms + 2*(d[r]-d[r+1])^2 per interior vertical
// pair (assigned to upper row) + d[0]^2 + d[127]^2 edge terms
// => band needs ONE bottom halo row only: overhead 1/32 = 3.1%
// (R2: 2/32 = 6.25%; v4's sync-based zero-halo lost 3.5us to CTA skew).
//
// Geometry = R2's measured-best: grid 4 bands x 32 batch = 128 blocks
// x 1024 threads. No cross-CTA sync anywhere.

#define HWROW4   128                 // 512-float raw row = 128 float4
#define CH4      (512 * HWROW4)      // float4 per channel
#define IMG4     (3 * CH4)           // float4 per image
#define PH       128                 // pooled H = W
#define BAND     32                  // pooled rows per block
#define TROWS    (BAND + 1)          // +1 bottom halo only
#define NPIX     (32 * PH * PH)
#define NBANDS   4
#define NBLOCKS  (NBANDS * 32)

__device__ float    g_acc;     // zero-init; last block resets
__device__ unsigned g_count;   // zero-init; last block resets

__global__ void __launch_bounds__(1024, 1) spa_fused_kernel(
    const float4* __restrict__ org, const float4* __restrict__ enh,
    float* __restrict__ out) {
    __shared__ float tile[TROWS][PH];      // 16896 B
    __shared__ float warp_sums[32];

    const int band = blockIdx.x;           // 0..3
    const int b    = blockIdx.y;           // 0..31
    const int tid  = threadIdx.x;
    const int s    = band * BAND;          // first pooled row of band
    const int ibase = b * IMG4;

    // ---- Phase 1: pool rows s .. s+32 (incl. 1 bottom halo row).
    // 33*128 = 4224 items over 1024 threads.
    for (int i = tid; i < TROWS * PH; i += 1024) {
        int r   = i >> 7;                  // 0..32
        int pw  = i & 127;
        int gph = s + r;
        float v = 0.0f;
        if (gph < PH) {                    // halo of last band: stays 0
            int base = ibase + (gph * 4) * HWROW4 + pw;
            float sum = 0.0f;
#pragma unroll
            for (int c = 0; c < 3; c++) {
#pragma unroll
                for (int dy = 0; dy < 4; dy++) {
                    float4 o = __ldg(&org[base + c * CH4 + dy * HWROW4]);
                    float4 e = __ldg(&enh[base + c * CH4 + dy * HWROW4]);
                    sum += (o.x - e.x) + (o.y - e.y) + (o.z - e.z) + (o.w - e.w);
                }
            }
            v = sum * (1.0f / 48.0f);
        }
        tile[r][pw] = v;
    }
    __syncthreads();

    // ---- Phase 2: loss over the 32 owned rows (4 full iterations).
    float t = 0.0f;
#pragma unroll
    for (int k = 0; k < (BAND * PH) / 1024; k++) {
        int i  = k * 1024 + tid;
        int r  = i >> 7;                   // 0..31
        int pw = i & 127;
        int gr = s + r;
        float c  = tile[r][pw];
        float l  = (pw > 0)      ? tile[r][pw - 1] : 0.0f;
        float rr = (pw < PH - 1) ? tile[r][pw + 1] : 0.0f;
        t += (c - l) * (c - l) + (c - rr) * (c - rr);
        if (gr + 1 < PH) {                 // vertical pair (gr,gr+1), x2
            float bl = tile[r + 1][pw];    // r=31 -> halo row
            t += 2.0f * (c - bl) * (c - bl);
        } else {                           // bottom image edge
            t += c * c;
        }
        if (gr == 0) t += c * c;           // top image edge
    }

    // ---- Phase 3: block reduce + last-block finalize.
#pragma unroll
    for (int off = 16; off > 0; off >>= 1)
        t += __shfl_down_sync(0xFFFFFFFFu, t, off);
    int lane = tid & 31, wid = tid >> 5;
    if (lane == 0) warp_sums[wid] = t;
    __syncthreads();
    if (wid == 0) {
        float v = warp_sums[lane];
#pragma unroll
        for (int off = 16; off > 0; off >>= 1)
            v += __shfl_down_sync(0xFFFFFFFFu, v, off);
        if (lane == 0) {
            atomicAdd(&g_acc, v);
            __threadfence();
            unsigned done = atomicAdd(&g_count, 1u);
            if (done == NBLOCKS - 1) {
                out[0] = g_acc * (1.0f / (float)NPIX);
                g_acc   = 0.0f;
                g_count = 0u;
            }
        }
    }
}

extern "C" void kernel_launch(void* const* d_in, const int* in_sizes, int n_in,
                              void* d_out, int out_size) {
    const float4* org = (const float4*)d_in[0];
    const float4* enh = (const float4*)d_in[1];
    float* out = (float*)d_out;
    spa_fused_kernel<<<dim3(NBANDS, 32), 1024>>>(org, enh, out);
}